// round 6
// baseline (speedup 1.0000x reference)
#include <cuda_runtime.h>
#include <cstdint>

// Problem constants (match reference)
#define BB 32
#define QQ 512
#define RR 1024
#define LL 1536
#define DD 2048
#define MAXRL 1024
#define GAMMA_F 0.99f
#define LMBDA_F 0.95f

// ---------------- output layout (flattened tuple, float32) ----------------
// values(B*R), value_pad_mask(B*R), value_last_pos(B), scores(B),
// response_last_pos(B), kl(B*R), kl_rewards(B*R), advantages(B*R), returns(B*R)
#define OFF_VAL 0
#define OFF_VPM (BB*RR)
#define OFF_VLP (2*BB*RR)
#define OFF_SC  (2*BB*RR + BB)
#define OFF_RLP (2*BB*RR + 2*BB)
#define OFF_KL  (2*BB*RR + 3*BB)
#define OFF_KLR (3*BB*RR + 3*BB)
#define OFF_ADV (4*BB*RR + 3*BB)
#define OFF_RET (5*BB*RR + 3*BB)

// ---------------- device scratch (no allocations allowed) ----------------
__device__ float  g_adv[BB*RR];
__device__ int    g_vlp[BB];
__device__ float  g_score[BB];
__device__ double g_psum[BB];
__device__ double g_psq[BB];
__device__ double g_pcnt[BB];

// ========================================================================
// K1: values_raw = hidden[:, Q-1 : L-1] . (w_base + w_adapter).
// Warp-per-row, 8 rows per 256-thread block, float4 loads. Writes the RAW
// dot product (masking applied later by k_gae) so this kernel has no
// dependency on mask metadata and can run first. DRAM-roofline kernel.
// ========================================================================
__global__ void __launch_bounds__(256) k_values(
    const float* __restrict__ hidden, const float* __restrict__ wb,
    const float* __restrict__ wa, float* __restrict__ out)
{
    __shared__ float ws[DD];
    int tid = threadIdx.x;
    #pragma unroll
    for (int i = tid; i < DD; i += 256) ws[i] = wb[i] + wa[i];
    __syncthreads();

    int warp = tid >> 5, lane = tid & 31;
    int row = blockIdx.x * 8 + warp;          // 0 .. 32767
    int b = row >> 10, t = row & 1023;
    const float4* h  = (const float4*)(hidden + ((size_t)b * LL + (QQ - 1) + t) * DD);
    const float4* w4 = (const float4*)ws;

    float acc = 0.f;
    #pragma unroll
    for (int k = 0; k < 16; k++) {
        int i4 = lane + k * 32;
        float4 v = h[i4];
        float4 w = w4[i4];
        acc += v.x * w.x + v.y * w.y + v.z * w.z + v.w * w.w;
    }
    #pragma unroll
    for (int o = 16; o; o >>= 1) acc += __shfl_down_sync(0xffffffffu, acc, o);

    if (lane == 0) out[OFF_VAL + row] = acc;   // raw, unmasked
}

// ========================================================================
// K2: fused meta + scores. One block per batch (256 threads).
// Phase 1: rlp / vlp / penalty from the int32-marshalled bool mask.
// Phase 2: scores[b] = hidden[b, rlp+Q] . w_base  (+ no-EOS penalty).
// ========================================================================
__global__ void __launch_bounds__(256) k_metascores(
    const float* __restrict__ hidden, const float* __restrict__ wb,
    const int* __restrict__ pad, float* __restrict__ out)
{
    __shared__ int s_last[8], s_any[8];
    __shared__ int sh_pos, sh_pen;
    __shared__ float red[8];

    int b = blockIdx.x, tid = threadIdx.x;
    int lane = tid & 31, warp = tid >> 5;

    // --- phase 1: mask metadata ---
    const int* p = pad + (size_t)b * RR;
    int last = -1, anyp = 0;
    #pragma unroll
    for (int i = tid; i < RR; i += 256) {
        int v = p[i];
        anyp |= v;
        if (!v) last = i;      // i strictly increasing per thread -> max survives
    }
    #pragma unroll
    for (int o = 16; o; o >>= 1) {
        last = max(last, __shfl_down_sync(0xffffffffu, last, o));
        anyp |= __shfl_down_sync(0xffffffffu, anyp, o);
    }
    if (lane == 0) { s_last[warp] = last; s_any[warp] = anyp; }
    __syncthreads();
    if (tid == 0) {
        int L = -1, A = 0;
        #pragma unroll
        for (int i = 0; i < 8; i++) { L = max(L, s_last[i]); A |= s_any[i]; }
        int rlp = L < 0 ? 0 : L;
        int vlp = (rlp > 0 && rlp < MAXRL - 1) ? rlp + 1 : rlp;
        g_vlp[b] = vlp;
        sh_pos = QQ + rlp;
        sh_pen = !A;                       // PENALISE_NO_EOS
        out[OFF_VLP + b] = (float)vlp;
        out[OFF_RLP + b] = (float)rlp;
    }
    __syncthreads();

    // --- phase 2: gathered score dot ---
    const float4* h  = (const float4*)(hidden + ((size_t)b * LL + sh_pos) * DD);
    const float4* w4 = (const float4*)wb;
    float acc = 0.f;
    #pragma unroll
    for (int i = tid; i < DD / 4; i += 256) {
        float4 v = h[i]; float4 w = w4[i];
        acc += v.x * w.x + v.y * w.y + v.z * w.z + v.w * w.w;
    }
    #pragma unroll
    for (int o = 16; o; o >>= 1) acc += __shfl_down_sync(0xffffffffu, acc, o);
    if (lane == 0) red[warp] = acc;
    __syncthreads();
    if (tid == 0) {
        float s = 0.f;
        #pragma unroll
        for (int i = 0; i < 8; i++) s += red[i];
        if (sh_pen) s = -3.0f;             // REWARD_PENALTY
        g_score[b] = s;
        out[OFF_SC + b] = s;
    }
}

// ========================================================================
// K3: warp-per-batch GAE, ZERO barriers. Each lane owns 32 contiguous
// timesteps in registers. Applies value masking fixup, emits
// values/vpm/kl/klr/returns, runs a weighted suffix scan:
//   1) sequential intra-lane suffix scan (32 FMAs),
//   2) 5-step shuffle scan over chunk heads with weight c^32,
//   3) per-element carry fixup with powers of c.
// Plus deterministic per-batch masked double partials for whitening.
// 8 blocks x 128 threads (4 warps = 4 batches per block).
// ========================================================================
__global__ void __launch_bounds__(128) k_gae(
    const float* __restrict__ gen, const float* __restrict__ ref,
    const int* __restrict__ pad, float* __restrict__ out)
{
    const float c = GAMMA_F * LMBDA_F;     // 0.9405
    int warp = threadIdx.x >> 5, lane = threadIdx.x & 31;
    int b = blockIdx.x * 4 + warp;
    int vlp = g_vlp[b];
    float score = g_score[b];
    int base = b * RR + lane * 32;         // first element this lane owns

    float vm[32];    // masked values
    float u[32];     // scan input, then reused as local suffix 'a'
    int   pd[32];

    // load raw values + mask, apply fixup, emit values/vpm/kl/klr
    #pragma unroll
    for (int j = 0; j < 32; j++) {
        int t = lane * 32 + j;
        int idx = base + j;
        float raw = out[OFF_VAL + idx];
        pd[j] = pad[idx];
        int vpm = (pd[j] != 0) && (t != vlp);
        vm[j] = vpm ? 0.f : raw;
        out[OFF_VAL + idx] = vm[j];
        out[OFF_VPM + idx] = vpm ? 1.f : 0.f;
        float kl  = gen[idx] - ref[idx];
        float klr = -0.1f * kl;            // KL_COEFF
        out[OFF_KL  + idx] = kl;
        out[OFF_KLR + idx] = klr;
        float r = klr + ((t == vlp) ? score : 0.f);
        u[j] = r - vm[j];                  // gamma*v_next added below
    }
    // v_next: vm[j+1] within chunk; first element of next lane's chunk for j=31
    float vnext0 = __shfl_down_sync(0xffffffffu, vm[0], 1);
    if (lane == 31) vnext0 = 0.f;          // v[1024] = 0
    #pragma unroll
    for (int j = 0; j < 31; j++) u[j] += GAMMA_F * vm[j + 1];
    u[31] += GAMMA_F * vnext0;

    // 1) intra-lane sequential suffix scan: a[j] = u[j] + c*a[j+1]
    #pragma unroll
    for (int j = 30; j >= 0; j--) u[j] += c * u[j + 1];

    // 2) warp-level weighted suffix scan of chunk heads (weight c^32)
    float x = u[0];
    float W = c;
    W = W * W; W = W * W; W = W * W; W = W * W; W = W * W;   // c^32
    #pragma unroll
    for (int o = 1; o < 32; o <<= 1) {
        float oth = __shfl_down_sync(0xffffffffu, x, o);
        x += W * ((lane + o < 32) ? oth : 0.f);
        W *= W;
    }
    // carry = adv at first element of NEXT chunk
    float carry = __shfl_down_sync(0xffffffffu, x, 1);
    if (lane == 31) carry = 0.f;

    // 3) fixup + outputs + masked double partials
    double da = 0.0, dq = 0.0, dn = 0.0;
    float pw = c;
    #pragma unroll
    for (int j = 31; j >= 0; j--) {
        float adv = u[j] + pw * carry;     // adv[t] = local + c^(32-j)*carry
        pw *= c;
        int idx = base + j;
        g_adv[idx] = adv;
        out[OFF_RET + idx] = adv + vm[j];
        if (pd[j] == 0) {
            da += (double)adv;
            dq += (double)adv * (double)adv;
            dn += 1.0;
        }
    }
    #pragma unroll
    for (int o = 16; o; o >>= 1) {
        da += __shfl_down_sync(0xffffffffu, da, o);
        dq += __shfl_down_sync(0xffffffffu, dq, o);
        dn += __shfl_down_sync(0xffffffffu, dn, o);
    }
    if (lane == 0) { g_psum[b] = da; g_psq[b] = dq; g_pcnt[b] = dn; }
}

// ========================================================================
// K4: masked whitening of advantages. 32 blocks x 1024. Each block sums
// the 32 per-batch partials (cheap, deterministic), then normalizes.
// ========================================================================
__global__ void __launch_bounds__(1024) k_whiten(
    const int* __restrict__ pad, float* __restrict__ out)
{
    __shared__ double sh_mean, sh_inv;
    if (threadIdx.x == 0) {
        double S = 0, Q2 = 0, N = 0;
        #pragma unroll
        for (int i = 0; i < BB; i++) { S += g_psum[i]; Q2 += g_psq[i]; N += g_pcnt[i]; }
        double mean = S / N;
        double var  = (Q2 / N - mean * mean) * (N / (N - 1.0));
        sh_mean = mean;
        sh_inv  = 1.0 / sqrt(var + 1e-8);
    }
    __syncthreads();
    int idx = blockIdx.x * 1024 + threadIdx.x;
    float adv = g_adv[idx];
    float w = (float)(((double)adv - sh_mean) * sh_inv);
    out[OFF_ADV + idx] = (pad[idx] == 0) ? w : 0.f;
}

// ========================================================================
extern "C" void kernel_launch(void* const* d_in, const int* in_sizes, int n_in,
                              void* d_out, int out_size) {
    const float* hidden = (const float*)d_in[0];
    const float* wb     = (const float*)d_in[1];
    const float* wa     = (const float*)d_in[2];
    const float* gen    = (const float*)d_in[3];
    const float* ref    = (const float*)d_in[4];
    const int*   pad    = (const int*)d_in[5];   // JAX bool -> int32 marshalling
    float* out = (float*)d_out;

    k_values    <<<BB * RR / 8, 256>>>(hidden, wb, wa, out);
    k_metascores<<<BB,          256>>>(hidden, wb, pad, out);
    k_gae       <<<8,           128>>>(gen, ref, pad, out);
    k_whiten    <<<BB,         1024>>>(pad, out);
}

// round 7
// speedup vs baseline: 1.3077x; 1.3077x over previous
#include <cuda_runtime.h>
#include <cstdint>

// Problem constants (match reference)
#define BB 32
#define QQ 512
#define RR 1024
#define LL 1536
#define DD 2048
#define MAXRL 1024
#define GAMMA_F 0.99f
#define LMBDA_F 0.95f

// ---------------- output layout (flattened tuple, float32) ----------------
#define OFF_VAL 0
#define OFF_VPM (BB*RR)
#define OFF_VLP (2*BB*RR)
#define OFF_SC  (2*BB*RR + BB)
#define OFF_RLP (2*BB*RR + 2*BB)
#define OFF_KL  (2*BB*RR + 3*BB)
#define OFF_KLR (3*BB*RR + 3*BB)
#define OFF_ADV (4*BB*RR + 3*BB)
#define OFF_RET (5*BB*RR + 3*BB)

// ---------------- device scratch (no allocations allowed) ----------------
__device__ float  g_adv[BB*RR];
__device__ int    g_vlp[BB];
__device__ float  g_score[BB];
__device__ double g_psum[BB];
__device__ double g_psq[BB];
__device__ double g_pcnt[BB];

// ========================================================================
// K1: values_raw = hidden[:, Q-1 : L-1] . (w_base + w_adapter).
// Warp-per-row, 8 rows per 256-thread block, float4 loads. RAW dot
// (masking applied later in k_gae). This is the DRAM-roofline kernel.
// ========================================================================
__global__ void __launch_bounds__(256) k_values(
    const float* __restrict__ hidden, const float* __restrict__ wb,
    const float* __restrict__ wa, float* __restrict__ out)
{
    __shared__ float ws[DD];
    int tid = threadIdx.x;
    #pragma unroll
    for (int i = tid; i < DD; i += 256) ws[i] = wb[i] + wa[i];
    __syncthreads();

    int warp = tid >> 5, lane = tid & 31;
    int row = blockIdx.x * 8 + warp;          // 0 .. 32767
    int b = row >> 10, t = row & 1023;
    const float4* h  = (const float4*)(hidden + ((size_t)b * LL + (QQ - 1) + t) * DD);
    const float4* w4 = (const float4*)ws;

    float acc = 0.f;
    #pragma unroll
    for (int k = 0; k < 16; k++) {
        int i4 = lane + k * 32;
        float4 v = h[i4];
        float4 w = w4[i4];
        acc += v.x * w.x + v.y * w.y + v.z * w.z + v.w * w.w;
    }
    #pragma unroll
    for (int o = 16; o; o >>= 1) acc += __shfl_down_sync(0xffffffffu, acc, o);

    if (lane == 0) out[OFF_VAL + row] = acc;   // raw, unmasked
}

// ========================================================================
// K2: fused meta + scores. One block per batch (256 threads).
// ========================================================================
__global__ void __launch_bounds__(256) k_metascores(
    const float* __restrict__ hidden, const float* __restrict__ wb,
    const int* __restrict__ pad, float* __restrict__ out)
{
    __shared__ int s_last[8], s_any[8];
    __shared__ int sh_pos, sh_pen;
    __shared__ float red[8];

    int b = blockIdx.x, tid = threadIdx.x;
    int lane = tid & 31, warp = tid >> 5;

    // --- phase 1: mask metadata ---
    const int* p = pad + (size_t)b * RR;
    int last = -1, anyp = 0;
    #pragma unroll
    for (int i = tid; i < RR; i += 256) {
        int v = p[i];
        anyp |= v;
        if (!v) last = i;
    }
    #pragma unroll
    for (int o = 16; o; o >>= 1) {
        last = max(last, __shfl_down_sync(0xffffffffu, last, o));
        anyp |= __shfl_down_sync(0xffffffffu, anyp, o);
    }
    if (lane == 0) { s_last[warp] = last; s_any[warp] = anyp; }
    __syncthreads();
    if (tid == 0) {
        int L = -1, A = 0;
        #pragma unroll
        for (int i = 0; i < 8; i++) { L = max(L, s_last[i]); A |= s_any[i]; }
        int rlp = L < 0 ? 0 : L;
        int vlp = (rlp > 0 && rlp < MAXRL - 1) ? rlp + 1 : rlp;
        g_vlp[b] = vlp;
        sh_pos = QQ + rlp;
        sh_pen = !A;                       // PENALISE_NO_EOS
        out[OFF_VLP + b] = (float)vlp;
        out[OFF_RLP + b] = (float)rlp;
    }
    __syncthreads();

    // --- phase 2: gathered score dot ---
    const float4* h  = (const float4*)(hidden + ((size_t)b * LL + sh_pos) * DD);
    const float4* w4 = (const float4*)wb;
    float acc = 0.f;
    #pragma unroll
    for (int i = tid; i < DD / 4; i += 256) {
        float4 v = h[i]; float4 w = w4[i];
        acc += v.x * w.x + v.y * w.y + v.z * w.z + v.w * w.w;
    }
    #pragma unroll
    for (int o = 16; o; o >>= 1) acc += __shfl_down_sync(0xffffffffu, acc, o);
    if (lane == 0) red[warp] = acc;
    __syncthreads();
    if (tid == 0) {
        float s = 0.f;
        #pragma unroll
        for (int i = 0; i < 8; i++) s += red[i];
        if (sh_pen) s = -3.0f;             // REWARD_PENALTY
        g_score[b] = s;
        out[OFF_SC + b] = s;
    }
}

// ========================================================================
// K3: GAE, one WARP per batch (32 blocks x 32 threads), all global traffic
// COALESCED via a stride-33 padded SMEM transpose (conflict-free).
//   pass 1 (coalesced, t = k*32+lane): mask fixup, emit values/vpm/kl/klr,
//          stage vm and u-partials into SMEM.
//   pass 2 (chunked from SMEM): intra-lane 32-FMA suffix scan, 5-step
//          shuffle head scan (weight c^32), carry fixup; stage adv back.
//   pass 3 (coalesced): emit adv/returns, masked double partials.
// Only __syncwarp()s; no block barriers.
// ========================================================================
__global__ void __launch_bounds__(32) k_gae(
    const float* __restrict__ gen, const float* __restrict__ ref,
    const int* __restrict__ pad, float* __restrict__ out)
{
    __shared__ float svm[32 * 33];   // vm, padded: element t at (t>>5)*33 + (t&31)
    __shared__ float su [32 * 33];   // u-partials, then reused for adv

    const float c = GAMMA_F * LMBDA_F;     // 0.9405
    int lane = threadIdx.x;
    int b = blockIdx.x;
    int vlp = g_vlp[b];
    float score = g_score[b];
    int base = b * RR;

    float vmk[32];   // vm at t = k*32+lane (coalesced ownership)
    int   pdk[32];

    // ---- pass 1: coalesced global, stage into SMEM ----
    #pragma unroll
    for (int k = 0; k < 32; k++) {
        int t = k * 32 + lane;
        int idx = base + t;
        float raw = out[OFF_VAL + idx];
        int p = pad[idx];
        int vpm = (p != 0) && (t != vlp);
        float vm = vpm ? 0.f : raw;
        vmk[k] = vm; pdk[k] = p;
        out[OFF_VAL + idx] = vm;
        out[OFF_VPM + idx] = vpm ? 1.f : 0.f;
        float kl  = gen[idx] - ref[idx];
        float klr = -0.1f * kl;            // KL_COEFF
        out[OFF_KL  + idx] = kl;
        out[OFF_KLR + idx] = klr;
        float r = klr + ((t == vlp) ? score : 0.f);
        svm[k * 33 + lane] = vm;
        su [k * 33 + lane] = r - vm;       // gamma*v_next added in pass 2
    }
    __syncwarp();

    // ---- pass 2: chunked from SMEM (lane owns t = lane*32 .. lane*32+31) ----
    float u[32];
    #pragma unroll
    for (int j = 0; j < 32; j++) {
        int pp = lane * 33 + j;
        float vnext = (j < 31) ? svm[pp + 1]
                    : (lane < 31 ? svm[(lane + 1) * 33] : 0.f);  // v[1024]=0
        u[j] = su[pp] + GAMMA_F * vnext;
    }
    // intra-lane suffix scan: a[j] = u[j] + c*a[j+1]
    #pragma unroll
    for (int j = 30; j >= 0; j--) u[j] += c * u[j + 1];

    // warp-level weighted suffix scan of chunk heads (weight c^32)
    float x = u[0];
    float W = c;
    W = W * W; W = W * W; W = W * W; W = W * W; W = W * W;   // c^32
    #pragma unroll
    for (int o = 1; o < 32; o <<= 1) {
        float oth = __shfl_down_sync(0xffffffffu, x, o);
        x += W * ((lane + o < 32) ? oth : 0.f);
        W *= W;
    }
    float carry = __shfl_down_sync(0xffffffffu, x, 1);  // adv at next chunk head
    if (lane == 31) carry = 0.f;

    __syncwarp();                       // done reading svm/su before overwrite
    float pw = c;
    #pragma unroll
    for (int j = 31; j >= 0; j--) {
        su[lane * 33 + j] = u[j] + pw * carry;   // adv[t] = local + c^(32-j)*carry
        pw *= c;
    }
    __syncwarp();

    // ---- pass 3: coalesced emit + masked double partials ----
    double da = 0.0, dq = 0.0, dn = 0.0;
    #pragma unroll
    for (int k = 0; k < 32; k++) {
        int idx = base + k * 32 + lane;
        float adv = su[k * 33 + lane];
        g_adv[idx] = adv;
        out[OFF_RET + idx] = adv + vmk[k];
        if (pdk[k] == 0) {
            da += (double)adv;
            dq += (double)adv * (double)adv;
            dn += 1.0;
        }
    }
    #pragma unroll
    for (int o = 16; o; o >>= 1) {
        da += __shfl_down_sync(0xffffffffu, da, o);
        dq += __shfl_down_sync(0xffffffffu, dq, o);
        dn += __shfl_down_sync(0xffffffffu, dn, o);
    }
    if (lane == 0) { g_psum[b] = da; g_psq[b] = dq; g_pcnt[b] = dn; }
}

// ========================================================================
// K4: masked whitening. 32 blocks x 256 threads, 4 elems/thread.
// Stats reduction parallelized across warp 0 (double shfl reduce) instead
// of a serial 96-DADD chain in thread 0.
// ========================================================================
__global__ void __launch_bounds__(256) k_whiten(
    const int* __restrict__ pad, float* __restrict__ out)
{
    __shared__ double sh_mean, sh_inv;
    int tid = threadIdx.x;
    if (tid < 32) {
        double da = g_psum[tid], dq = g_psq[tid], dn = g_pcnt[tid];
        #pragma unroll
        for (int o = 16; o; o >>= 1) {
            da += __shfl_down_sync(0xffffffffu, da, o);
            dq += __shfl_down_sync(0xffffffffu, dq, o);
            dn += __shfl_down_sync(0xffffffffu, dn, o);
        }
        if (tid == 0) {
            double mean = da / dn;
            double var  = (dq / dn - mean * mean) * (dn / (dn - 1.0));
            sh_mean = mean;
            sh_inv  = 1.0 / sqrt(var + 1e-8);
        }
    }
    __syncthreads();
    double mean = sh_mean, inv = sh_inv;
    #pragma unroll
    for (int k = 0; k < 4; k++) {
        int idx = (blockIdx.x * 4 + k) * 256 + tid;
        float adv = g_adv[idx];
        float w = (float)(((double)adv - mean) * inv);
        out[OFF_ADV + idx] = (pad[idx] == 0) ? w : 0.f;
    }
}

// ========================================================================
extern "C" void kernel_launch(void* const* d_in, const int* in_sizes, int n_in,
                              void* d_out, int out_size) {
    const float* hidden = (const float*)d_in[0];
    const float* wb     = (const float*)d_in[1];
    const float* wa     = (const float*)d_in[2];
    const float* gen    = (const float*)d_in[3];
    const float* ref    = (const float*)d_in[4];
    const int*   pad    = (const int*)d_in[5];   // JAX bool -> int32 marshalling
    float* out = (float*)d_out;

    k_values    <<<BB * RR / 8, 256>>>(hidden, wb, wa, out);
    k_metascores<<<BB,          256>>>(hidden, wb, pad, out);
    k_gae       <<<BB,           32>>>(gen, ref, pad, out);
    k_whiten    <<<BB,          256>>>(pad, out);
}

// round 9
// speedup vs baseline: 1.3607x; 1.0406x over previous
#include <cuda_runtime.h>
#include <cstdint>

// Problem constants (match reference)
#define BB 32
#define QQ 512
#define RR 1024
#define LL 1536
#define DD 2048
#define MAXRL 1024
#define GAMMA_F 0.99f
#define LMBDA_F 0.95f

// ---------------- output layout (flattened tuple, float32) ----------------
#define OFF_VAL 0
#define OFF_VPM (BB*RR)
#define OFF_VLP (2*BB*RR)
#define OFF_SC  (2*BB*RR + BB)
#define OFF_RLP (2*BB*RR + 2*BB)
#define OFF_KL  (2*BB*RR + 3*BB)
#define OFF_KLR (3*BB*RR + 3*BB)
#define OFF_ADV (4*BB*RR + 3*BB)
#define OFF_RET (5*BB*RR + 3*BB)

// ---------------- device scratch (no allocations allowed) ----------------
__device__ int      g_vlp[BB];
__device__ float    g_score[BB];
__device__ double   g_psum[BB];
__device__ double   g_psq[BB];
__device__ double   g_pcnt[BB];
__device__ unsigned g_ctr;     // monotonic epoch counter for grid barrier
                               // (zero-init at module load; +32 per launch,
                               //  replay-safe without reset)

// ========================================================================
// K_A: block-specialized fusion.
//   blocks 0..4095  : values_raw = hidden[:, Q-1:L-1] . (wb+wa), warp-per-row
//                     (8 rows / 256-thread block, float4). RAW dot; masking
//                     is applied later in K_B. DRAM-roofline path.
//   blocks 4096..4127: per-batch meta (rlp/vlp/penalty from int32 bool mask)
//                     + gathered score dot with w_base.
// ========================================================================
__global__ void __launch_bounds__(256) k_main(
    const float* __restrict__ hidden, const float* __restrict__ wb,
    const float* __restrict__ wa, const int* __restrict__ pad,
    float* __restrict__ out)
{
    int tid = threadIdx.x;
    int lane = tid & 31, warp = tid >> 5;

    if (blockIdx.x < BB * RR / 8) {
        // ---------------- values path ----------------
        __shared__ float ws[DD];
        #pragma unroll
        for (int i = tid; i < DD; i += 256) ws[i] = wb[i] + wa[i];
        __syncthreads();

        int row = blockIdx.x * 8 + warp;          // 0 .. 32767
        int b = row >> 10, t = row & 1023;
        const float4* h  = (const float4*)(hidden + ((size_t)b * LL + (QQ - 1) + t) * DD);
        const float4* w4 = (const float4*)ws;

        float acc = 0.f;
        #pragma unroll
        for (int k = 0; k < 16; k++) {
            int i4 = lane + k * 32;
            float4 v = h[i4];
            float4 w = w4[i4];
            acc += v.x * w.x + v.y * w.y + v.z * w.z + v.w * w.w;
        }
        #pragma unroll
        for (int o = 16; o; o >>= 1) acc += __shfl_down_sync(0xffffffffu, acc, o);
        if (lane == 0) out[OFF_VAL + row] = acc;   // raw, unmasked
    } else {
        // ---------------- meta + scores path ----------------
        __shared__ int s_last[8], s_any[8];
        __shared__ int sh_pos, sh_pen;
        __shared__ float red[8];

        int b = blockIdx.x - BB * RR / 8;

        const int* p = pad + (size_t)b * RR;
        int last = -1, anyp = 0;
        #pragma unroll
        for (int i = tid; i < RR; i += 256) {
            int v = p[i];
            anyp |= v;
            if (!v) last = i;      // i strictly increasing -> max survives
        }
        #pragma unroll
        for (int o = 16; o; o >>= 1) {
            last = max(last, __shfl_down_sync(0xffffffffu, last, o));
            anyp |= __shfl_down_sync(0xffffffffu, anyp, o);
        }
        if (lane == 0) { s_last[warp] = last; s_any[warp] = anyp; }
        __syncthreads();
        if (tid == 0) {
            int L = -1, A = 0;
            #pragma unroll
            for (int i = 0; i < 8; i++) { L = max(L, s_last[i]); A |= s_any[i]; }
            int rlp = L < 0 ? 0 : L;
            int vlp = (rlp > 0 && rlp < MAXRL - 1) ? rlp + 1 : rlp;
            g_vlp[b] = vlp;
            sh_pos = QQ + rlp;
            sh_pen = !A;                       // PENALISE_NO_EOS
            out[OFF_VLP + b] = (float)vlp;
            out[OFF_RLP + b] = (float)rlp;
        }
        __syncthreads();

        const float4* h  = (const float4*)(hidden + ((size_t)b * LL + sh_pos) * DD);
        const float4* w4 = (const float4*)wb;
        float acc = 0.f;
        #pragma unroll
        for (int i = tid; i < DD / 4; i += 256) {
            float4 v = h[i]; float4 w = w4[i];
            acc += v.x * w.x + v.y * w.y + v.z * w.z + v.w * w.w;
        }
        #pragma unroll
        for (int o = 16; o; o >>= 1) acc += __shfl_down_sync(0xffffffffu, acc, o);
        if (lane == 0) red[warp] = acc;
        __syncthreads();
        if (tid == 0) {
            float s = 0.f;
            #pragma unroll
            for (int i = 0; i < 8; i++) s += red[i];
            if (sh_pen) s = -3.0f;             // REWARD_PENALTY
            g_score[b] = s;
            out[OFF_SC + b] = s;
        }
    }
}

// ========================================================================
// K_B: GAE + whitening fused. One WARP per batch, 32 blocks x 32 threads
// (all resident -> safe grid barrier). All global traffic coalesced via a
// stride-33 padded SMEM transpose.
//   pass 1 (coalesced): mask fixup, emit values/vpm/kl/klr, stage vm & u.
//   pass 2 (chunked, SMEM): 32-FMA intra-lane suffix scan, 5-step shuffle
//          head scan (weight c^32), carry fixup; stage adv back into SMEM.
//   pass 3 (coalesced): emit returns, masked double partials -> globals.
//   grid barrier (monotonic epoch counter, replay-safe, no reset).
//   pass 4: every block redundantly shuffle-reduces the 32 partials
//          (bitwise-identical mean/inv), normalizes its batch's adv from
//          SMEM, emits advantages. adv never round-trips DRAM.
// ========================================================================
__global__ void __launch_bounds__(32) k_gae_whiten(
    const float* __restrict__ gen, const float* __restrict__ ref,
    const int* __restrict__ pad, float* __restrict__ out)
{
    __shared__ float svm[32 * 33];   // vm, padded: element t at (t>>5)*33 + (t&31)
    __shared__ float su [32 * 33];   // u-partials, then reused for adv

    const float c = GAMMA_F * LMBDA_F;     // 0.9405
    int lane = threadIdx.x;
    int b = blockIdx.x;
    int vlp = g_vlp[b];
    float score = g_score[b];
    int base = b * RR;

    float vmk[32];   // vm at t = k*32+lane (coalesced ownership)
    int   pdk[32];

    // ---- pass 1: coalesced global, stage into SMEM ----
    #pragma unroll
    for (int k = 0; k < 32; k++) {
        int t = k * 32 + lane;
        int idx = base + t;
        float raw = out[OFF_VAL + idx];
        int p = pad[idx];
        int vpm = (p != 0) && (t != vlp);
        float vm = vpm ? 0.f : raw;
        vmk[k] = vm; pdk[k] = p;
        out[OFF_VAL + idx] = vm;
        out[OFF_VPM + idx] = vpm ? 1.f : 0.f;
        float kl  = gen[idx] - ref[idx];
        float klr = -0.1f * kl;            // KL_COEFF
        out[OFF_KL  + idx] = kl;
        out[OFF_KLR + idx] = klr;
        float r = klr + ((t == vlp) ? score : 0.f);
        svm[k * 33 + lane] = vm;
        su [k * 33 + lane] = r - vm;       // gamma*v_next added in pass 2
    }
    __syncwarp();

    // ---- pass 2: chunked from SMEM (lane owns t = lane*32 .. lane*32+31) ----
    float u[32];
    #pragma unroll
    for (int j = 0; j < 32; j++) {
        int pp = lane * 33 + j;
        float vnext = (j < 31) ? svm[pp + 1]
                    : (lane < 31 ? svm[(lane + 1) * 33] : 0.f);  // v[1024]=0
        u[j] = su[pp] + GAMMA_F * vnext;
    }
    #pragma unroll
    for (int j = 30; j >= 0; j--) u[j] += c * u[j + 1];   // intra-lane suffix scan

    float x = u[0];
    float W = c;
    W = W * W; W = W * W; W = W * W; W = W * W; W = W * W;   // c^32
    #pragma unroll
    for (int o = 1; o < 32; o <<= 1) {
        float oth = __shfl_down_sync(0xffffffffu, x, o);
        x += W * ((lane + o < 32) ? oth : 0.f);
        W *= W;
    }
    float carry = __shfl_down_sync(0xffffffffu, x, 1);  // adv at next chunk head
    if (lane == 31) carry = 0.f;

    __syncwarp();                       // done reading svm/su before overwrite
    float pw = c;
    #pragma unroll
    for (int j = 31; j >= 0; j--) {
        su[lane * 33 + j] = u[j] + pw * carry;   // adv[t] = local + c^(32-j)*carry
        pw *= c;
    }
    __syncwarp();

    // ---- pass 3: coalesced returns + masked double partials ----
    double da = 0.0, dq = 0.0, dn = 0.0;
    #pragma unroll
    for (int k = 0; k < 32; k++) {
        int idx = base + k * 32 + lane;
        float adv = su[k * 33 + lane];
        out[OFF_RET + idx] = adv + vmk[k];
        if (pdk[k] == 0) {
            da += (double)adv;
            dq += (double)adv * (double)adv;
            dn += 1.0;
        }
    }
    #pragma unroll
    for (int o = 16; o; o >>= 1) {
        da += __shfl_down_sync(0xffffffffu, da, o);
        dq += __shfl_down_sync(0xffffffffu, dq, o);
        dn += __shfl_down_sync(0xffffffffu, dn, o);
    }
    if (lane == 0) { g_psum[b] = da; g_psq[b] = dq; g_pcnt[b] = dn; }

    // ---- grid barrier: monotonic epoch counter, replay-safe ----
    __threadfence();                      // partials visible before arrive
    unsigned my = 0;
    if (lane == 0) my = atomicAdd(&g_ctr, 1u);
    my = __shfl_sync(0xffffffffu, my, 0);
    unsigned target = ((my >> 5) + 1u) << 5;   // next multiple of 32
    if (lane == 0) {
        while (*(volatile unsigned*)&g_ctr < target) { }
    }
    __syncwarp();
    __threadfence();                      // acquire: partials now readable

    // ---- pass 4: redundant stats + whiten from SMEM ----
    double ra = *(volatile double*)&g_psum[lane];
    double rq = *(volatile double*)&g_psq [lane];
    double rn = *(volatile double*)&g_pcnt[lane];
    #pragma unroll
    for (int o = 16; o; o >>= 1) {
        ra += __shfl_down_sync(0xffffffffu, ra, o);
        rq += __shfl_down_sync(0xffffffffu, rq, o);
        rn += __shfl_down_sync(0xffffffffu, rn, o);
    }
    double mean, inv;
    if (lane == 0) {
        mean = ra / rn;
        double var = (rq / rn - mean * mean) * (rn / (rn - 1.0));
        inv = 1.0 / sqrt(var + 1e-8);
    }
    mean = __shfl_sync(0xffffffffu, mean, 0);
    inv  = __shfl_sync(0xffffffffu, inv, 0);

    #pragma unroll
    for (int k = 0; k < 32; k++) {
        int idx = base + k * 32 + lane;
        float adv = su[k * 33 + lane];
        float w = (float)(((double)adv - mean) * inv);
        out[OFF_ADV + idx] = (pdk[k] == 0) ? w : 0.f;
    }
}

// ========================================================================
extern "C" void kernel_launch(void* const* d_in, const int* in_sizes, int n_in,
                              void* d_out, int out_size) {
    const float* hidden = (const float*)d_in[0];
    const float* wb     = (const float*)d_in[1];
    const float* wa     = (const float*)d_in[2];
    const float* gen    = (const float*)d_in[3];
    const float* ref    = (const float*)d_in[4];
    const int*   pad    = (const int*)d_in[5];   // JAX bool -> int32 marshalling
    float* out = (float*)d_out;

    k_main      <<<BB * RR / 8 + BB, 256>>>(hidden, wb, wa, pad, out);
    k_gae_whiten<<<BB,                32>>>(gen, ref, pad, out);
}

// round 10
// speedup vs baseline: 1.5569x; 1.1441x over previous
#include <cuda_runtime.h>
#include <cstdint>

// Problem constants (match reference)
#define BB 32
#define QQ 512
#define RR 1024
#define LL 1536
#define DD 2048
#define MAXRL 1024
#define GAMMA_F 0.99f
#define LMBDA_F 0.95f

// ---------------- output layout (flattened tuple, float32) ----------------
#define OFF_VAL 0
#define OFF_VPM (BB*RR)
#define OFF_VLP (2*BB*RR)
#define OFF_SC  (2*BB*RR + BB)
#define OFF_RLP (2*BB*RR + 2*BB)
#define OFF_KL  (2*BB*RR + 3*BB)
#define OFF_KLR (3*BB*RR + 3*BB)
#define OFF_ADV (4*BB*RR + 3*BB)
#define OFF_RET (5*BB*RR + 3*BB)

// ---------------- device scratch (no allocations allowed) ----------------
__device__ int      g_vlp[BB];
__device__ float    g_score[BB];
__device__ double   g_psum[BB];
__device__ double   g_psq[BB];
__device__ double   g_pcnt[BB];
__device__ unsigned g_ctr;     // monotonic epoch counter for grid barrier
                               // (zero-init; +32 per launch, replay-safe)

// ========================================================================
// K_A: block-specialized fusion.
//   blocks 0..4095  : values_raw = hidden[:, Q-1:L-1] . (wb+wa), warp-per-row
//                     (8 rows / 256-thread block, float4). RAW dot; masking
//                     is applied later in K_B. DRAM-roofline path.
//   blocks 4096..4127: per-batch meta (rlp/vlp/penalty from int32 bool mask)
//                     + gathered score dot with w_base.
// ========================================================================
__global__ void __launch_bounds__(256) k_main(
    const float* __restrict__ hidden, const float* __restrict__ wb,
    const float* __restrict__ wa, const int* __restrict__ pad,
    float* __restrict__ out)
{
    int tid = threadIdx.x;
    int lane = tid & 31, warp = tid >> 5;

    if (blockIdx.x < BB * RR / 8) {
        // ---------------- values path ----------------
        __shared__ float ws[DD];
        #pragma unroll
        for (int i = tid; i < DD; i += 256) ws[i] = wb[i] + wa[i];
        __syncthreads();

        int row = blockIdx.x * 8 + warp;          // 0 .. 32767
        int b = row >> 10, t = row & 1023;
        const float4* h  = (const float4*)(hidden + ((size_t)b * LL + (QQ - 1) + t) * DD);
        const float4* w4 = (const float4*)ws;

        float acc = 0.f;
        #pragma unroll
        for (int k = 0; k < 16; k++) {
            int i4 = lane + k * 32;
            float4 v = h[i4];
            float4 w = w4[i4];
            acc += v.x * w.x + v.y * w.y + v.z * w.z + v.w * w.w;
        }
        #pragma unroll
        for (int o = 16; o; o >>= 1) acc += __shfl_down_sync(0xffffffffu, acc, o);
        if (lane == 0) out[OFF_VAL + row] = acc;   // raw, unmasked
    } else {
        // ---------------- meta + scores path ----------------
        __shared__ int s_last[8], s_any[8];
        __shared__ int sh_pos, sh_pen;
        __shared__ float red[8];

        int b = blockIdx.x - BB * RR / 8;

        const int* p = pad + (size_t)b * RR;
        int last = -1, anyp = 0;
        #pragma unroll
        for (int i = tid; i < RR; i += 256) {
            int v = p[i];
            anyp |= v;
            if (!v) last = i;      // i strictly increasing -> max survives
        }
        #pragma unroll
        for (int o = 16; o; o >>= 1) {
            last = max(last, __shfl_down_sync(0xffffffffu, last, o));
            anyp |= __shfl_down_sync(0xffffffffu, anyp, o);
        }
        if (lane == 0) { s_last[warp] = last; s_any[warp] = anyp; }
        __syncthreads();
        if (tid == 0) {
            int L = -1, A = 0;
            #pragma unroll
            for (int i = 0; i < 8; i++) { L = max(L, s_last[i]); A |= s_any[i]; }
            int rlp = L < 0 ? 0 : L;
            int vlp = (rlp > 0 && rlp < MAXRL - 1) ? rlp + 1 : rlp;
            g_vlp[b] = vlp;
            sh_pos = QQ + rlp;
            sh_pen = !A;                       // PENALISE_NO_EOS
            out[OFF_VLP + b] = (float)vlp;
            out[OFF_RLP + b] = (float)rlp;
        }
        __syncthreads();

        const float4* h  = (const float4*)(hidden + ((size_t)b * LL + sh_pos) * DD);
        const float4* w4 = (const float4*)wb;
        float acc = 0.f;
        #pragma unroll
        for (int i = tid; i < DD / 4; i += 256) {
            float4 v = h[i]; float4 w = w4[i];
            acc += v.x * w.x + v.y * w.y + v.z * w.z + v.w * w.w;
        }
        #pragma unroll
        for (int o = 16; o; o >>= 1) acc += __shfl_down_sync(0xffffffffu, acc, o);
        if (lane == 0) red[warp] = acc;
        __syncthreads();
        if (tid == 0) {
            float s = 0.f;
            #pragma unroll
            for (int i = 0; i < 8; i++) s += red[i];
            if (sh_pen) s = -3.0f;             // REWARD_PENALTY
            g_score[b] = s;
            out[OFF_SC + b] = s;
        }
    }
}

// ========================================================================
// K_B: GAE + whitening fused. One 256-THREAD block per batch (32 blocks,
// all resident -> safe grid barrier). Memory passes use all 8 warps
// (4 elems/thread, coalesced, 8x the MLP of a single warp); only the scan
// itself runs on warp 0. SMEM staging stride-33 (conflict-free transpose).
//   pass 1 (256T): mask fixup, emit values/vpm/kl/klr, stage vm & u.
//   pass 2 (warp 0): 32-FMA intra-lane suffix scan, 5-step shuffle head
//          scan (weight c^32), carry fixup; adv back into SMEM.
//   pass 3 (256T): emit returns, masked double partials (deterministic
//          8-warp block reduce) -> globals.
//   grid barrier (monotonic epoch counter, replay-safe).
//   pass 4 (256T): redundant stats reduce, whiten from SMEM, emit adv.
// ========================================================================
__global__ void __launch_bounds__(256) k_gae_whiten(
    const float* __restrict__ gen, const float* __restrict__ ref,
    const int* __restrict__ pad, float* __restrict__ out)
{
    __shared__ float svm[32 * 33];    // vm: element t at (t>>5)*33 + (t&31)
    __shared__ float su [32 * 33];    // u-partials, then reused for adv
    __shared__ double s_red[3][8];
    __shared__ double sh_mean, sh_inv;

    const float c = GAMMA_F * LMBDA_F;     // 0.9405
    int tid = threadIdx.x;
    int lane = tid & 31, warp = tid >> 5;
    int b = blockIdx.x;
    int vlp = g_vlp[b];
    float score = g_score[b];
    int base = b * RR;

    float vmk[4];
    int   pdk[4];

    // ---- pass 1: all threads, coalesced (t = k*256 + tid) ----
    #pragma unroll
    for (int k = 0; k < 4; k++) {
        int t = k * 256 + tid;
        int idx = base + t;
        float raw = out[OFF_VAL + idx];
        int p = pad[idx];
        int vpm = (p != 0) && (t != vlp);
        float vm = vpm ? 0.f : raw;
        vmk[k] = vm; pdk[k] = p;
        out[OFF_VAL + idx] = vm;
        out[OFF_VPM + idx] = vpm ? 1.f : 0.f;
        float kl  = gen[idx] - ref[idx];
        float klr = -0.1f * kl;            // KL_COEFF
        out[OFF_KL  + idx] = kl;
        out[OFF_KLR + idx] = klr;
        float r = klr + ((t == vlp) ? score : 0.f);
        int pp = (t >> 5) * 33 + (t & 31);
        svm[pp] = vm;
        su [pp] = r - vm;                  // gamma*v_next added in pass 2
    }
    __syncthreads();

    // ---- pass 2: scan on warp 0 only ----
    if (warp == 0) {
        float u[32];
        #pragma unroll
        for (int j = 0; j < 32; j++) {
            int pp = lane * 33 + j;
            float vnext = (j < 31) ? svm[pp + 1]
                        : (lane < 31 ? svm[(lane + 1) * 33] : 0.f);  // v[1024]=0
            u[j] = su[pp] + GAMMA_F * vnext;
        }
        #pragma unroll
        for (int j = 30; j >= 0; j--) u[j] += c * u[j + 1];   // intra-lane scan

        float x = u[0];
        float W = c;
        W = W * W; W = W * W; W = W * W; W = W * W; W = W * W;   // c^32
        #pragma unroll
        for (int o = 1; o < 32; o <<= 1) {
            float oth = __shfl_down_sync(0xffffffffu, x, o);
            x += W * ((lane + o < 32) ? oth : 0.f);
            W *= W;
        }
        float carry = __shfl_down_sync(0xffffffffu, x, 1);
        if (lane == 31) carry = 0.f;

        float pw = c;
        #pragma unroll
        for (int j = 31; j >= 0; j--) {
            su[lane * 33 + j] = u[j] + pw * carry;   // adv
            pw *= c;
        }
    }
    __syncthreads();

    // ---- pass 3: all threads, returns + masked double partials ----
    double da = 0.0, dq = 0.0, dn = 0.0;
    float advk[4];
    #pragma unroll
    for (int k = 0; k < 4; k++) {
        int t = k * 256 + tid;
        int idx = base + t;
        float adv = su[(t >> 5) * 33 + (t & 31)];
        advk[k] = adv;
        out[OFF_RET + idx] = adv + vmk[k];
        if (pdk[k] == 0) {
            da += (double)adv;
            dq += (double)adv * (double)adv;
            dn += 1.0;
        }
    }
    #pragma unroll
    for (int o = 16; o; o >>= 1) {
        da += __shfl_down_sync(0xffffffffu, da, o);
        dq += __shfl_down_sync(0xffffffffu, dq, o);
        dn += __shfl_down_sync(0xffffffffu, dn, o);
    }
    if (lane == 0) { s_red[0][warp] = da; s_red[1][warp] = dq; s_red[2][warp] = dn; }
    __syncthreads();
    if (tid == 0) {
        double S = 0, Q2 = 0, N = 0;
        #pragma unroll
        for (int i = 0; i < 8; i++) { S += s_red[0][i]; Q2 += s_red[1][i]; N += s_red[2][i]; }
        g_psum[b] = S; g_psq[b] = Q2; g_pcnt[b] = N;
        __threadfence();                              // partials visible
    }
    __syncthreads();

    // ---- grid barrier: monotonic epoch counter, replay-safe ----
    if (tid == 0) {
        unsigned my = atomicAdd(&g_ctr, 1u);
        unsigned target = ((my >> 5) + 1u) << 5;      // next multiple of 32
        while (*(volatile unsigned*)&g_ctr < target) { }
    }
    __syncthreads();
    __threadfence();                                  // acquire partials

    // ---- pass 4: redundant stats (warp 0) + whiten all threads ----
    if (tid < 32) {
        double ra = *(volatile double*)&g_psum[tid];
        double rq = *(volatile double*)&g_psq [tid];
        double rn = *(volatile double*)&g_pcnt[tid];
        #pragma unroll
        for (int o = 16; o; o >>= 1) {
            ra += __shfl_down_sync(0xffffffffu, ra, o);
            rq += __shfl_down_sync(0xffffffffu, rq, o);
            rn += __shfl_down_sync(0xffffffffu, rn, o);
        }
        if (tid == 0) {
            double mean = ra / rn;
            double var  = (rq / rn - mean * mean) * (rn / (rn - 1.0));
            sh_mean = mean;
            sh_inv  = 1.0 / sqrt(var + 1e-8);
        }
    }
    __syncthreads();
    double mean = sh_mean, inv = sh_inv;
    #pragma unroll
    for (int k = 0; k < 4; k++) {
        int idx = base + k * 256 + tid;
        float w = (float)(((double)advk[k] - mean) * inv);
        out[OFF_ADV + idx] = (pdk[k] == 0) ? w : 0.f;
    }
}

// ========================================================================
extern "C" void kernel_launch(void* const* d_in, const int* in_sizes, int n_in,
                              void* d_out, int out_size) {
    const float* hidden = (const float*)d_in[0];
    const float* wb     = (const float*)d_in[1];
    const float* wa     = (const float*)d_in[2];
    const float* gen    = (const float*)d_in[3];
    const float* ref    = (const float*)d_in[4];
    const int*   pad    = (const int*)d_in[5];   // JAX bool -> int32 marshalling
    float* out = (float*)d_out;

    k_main      <<<BB * RR / 8 + BB, 256>>>(hidden, wb, wa, pad, out);
    k_gae_whiten<<<BB,               256>>>(gen, ref, pad, out);
}